// round 14
// baseline (speedup 1.0000x reference)
#include <cuda_runtime.h>
#include <cuda_bf16.h>

#define GEPS 1e-8f
constexpr int BS    = 128;         // 4 warps
constexpr int WARPS = BS / 32;

__device__ __forceinline__ void cov_from_q(
    float4 qv, float sa, float sb, float sc, float* __restrict__ o /* 9 floats */)
{
    float w = qv.x, x = qv.y, y = qv.z, z = qv.w;
    float inv = rsqrtf(w * w + x * x + y * y + z * z);
    w *= inv; x *= inv; y *= inv; z *= inv;

    const float r00 = 1.f - 2.f * (y * y + z * z);
    const float r01 = 2.f * (x * y - w * z);
    const float r02 = 2.f * (x * z + w * y);
    const float r10 = 2.f * (x * y + w * z);
    const float r11 = 1.f - 2.f * (x * x + z * z);
    const float r12 = 2.f * (y * z - w * x);
    const float r20 = 2.f * (x * z - w * y);
    const float r21 = 2.f * (y * z + w * x);
    const float r22 = 1.f - 2.f * (x * x + y * y);

    sa = fabsf(sa) + GEPS;
    sb = fabsf(sb) + GEPS;
    sc = fabsf(sc) + GEPS;
    const float a = sa * sa, b = sb * sb, c = sc * sc;

    const float m00 = r00 * r00 * a + r01 * r01 * b + r02 * r02 * c;
    const float m01 = r00 * r10 * a + r01 * r11 * b + r02 * r12 * c;
    const float m02 = r00 * r20 * a + r01 * r21 * b + r02 * r22 * c;
    const float m11 = r10 * r10 * a + r11 * r11 * b + r12 * r12 * c;
    const float m12 = r10 * r20 * a + r11 * r21 * b + r12 * r22 * c;
    const float m22 = r20 * r20 * a + r21 * r21 * b + r22 * r22 * c;

    o[0] = m00; o[1] = m01; o[2] = m02;
    o[3] = m01; o[4] = m11; o[5] = m12;
    o[6] = m02; o[7] = m12; o[8] = m22;
}

__global__ __launch_bounds__(BS) void gaussians_cov_kernel(
    const float4* __restrict__ q,     // [N] float4 (w,x,y,z)
    const float*  __restrict__ s,     // [N*3]
    float*        __restrict__ out,   // [N*9]
    int N)
{
    // warp-private output staging only; no block-wide barriers anywhere
    __shared__ __align__(16) float osm[WARPS][32 * 9];   // 4 * 1152 B = 4.5 KB

    const int tid   = threadIdx.x;
    const int wid   = tid >> 5;
    const int lane  = tid & 31;
    const int base  = blockIdx.x * BS + wid * 32;   // this warp's 32 points
    const bool full = (base + 32) <= N;

    if (full) {
        const int n = base + lane;

        // ---- front-batch 4 independent loads per thread ----
        // q: perfect float4 coalescing. scales: warp's 3 stride-3 scalar LDGs
        // touch only 3 unique 128B lines (L1-merged) -> same DRAM traffic.
        float4 qv = q[n];
        float sa = __ldg(&s[n * 3 + 0]);
        float sb = __ldg(&s[n * 3 + 1]);
        float sc = __ldg(&s[n * 3 + 2]);

        // ---- compute, stage to warp-private smem (stride 9: conflict-free) ----
        cov_from_q(qv, sa, sb, sc, &osm[wid][lane * 9]);
        __syncwarp();

        // ---- warp-cooperative coalesced store: 288 floats = 72 float4 ----
        float4*       out4 = reinterpret_cast<float4*>(out) + (size_t)base * 9 / 4;
        const float4* osm4 = reinterpret_cast<const float4*>(osm[wid]);
        out4[lane]      = osm4[lane];
        out4[32 + lane] = osm4[32 + lane];
        if (lane < 8) out4[64 + lane] = osm4[64 + lane];
    } else {
        const int n = base + lane;
        if (n < N) {
            float4 qv = q[n];
            float obuf[9];
            cov_from_q(qv, s[n * 3 + 0], s[n * 3 + 1], s[n * 3 + 2], obuf);
            float* o = out + (size_t)n * 9;
            #pragma unroll
            for (int j = 0; j < 9; ++j) o[j] = obuf[j];
        }
    }
}

extern "C" void kernel_launch(void* const* d_in, const int* in_sizes, int n_in,
                              void* d_out, int out_size) {
    const float4* q = (const float4*)d_in[0];   // quaternion [N,4]
    const float*  s = (const float*)d_in[1];    // scale [N,3]
    float* out = (float*)d_out;                 // [N,3,3]
    const int N = in_sizes[0] / 4;

    const int grid = (N + BS - 1) / BS;
    gaussians_cov_kernel<<<grid, BS>>>(q, s, out, N);
}

// round 15
// speedup vs baseline: 1.1367x; 1.1367x over previous
#include <cuda_runtime.h>
#include <cuda_bf16.h>

#define GEPS 1e-8f
constexpr int BS    = 256;         // 8 warps
constexpr int WARPS = BS / 32;

__device__ __forceinline__ void cov_from_q(
    float4 qv, float sa, float sb, float sc, float* __restrict__ o /* 9 floats */)
{
    float w = qv.x, x = qv.y, y = qv.z, z = qv.w;
    float inv = rsqrtf(w * w + x * x + y * y + z * z);
    w *= inv; x *= inv; y *= inv; z *= inv;

    const float r00 = 1.f - 2.f * (y * y + z * z);
    const float r01 = 2.f * (x * y - w * z);
    const float r02 = 2.f * (x * z + w * y);
    const float r10 = 2.f * (x * y + w * z);
    const float r11 = 1.f - 2.f * (x * x + z * z);
    const float r12 = 2.f * (y * z - w * x);
    const float r20 = 2.f * (x * z - w * y);
    const float r21 = 2.f * (y * z + w * x);
    const float r22 = 1.f - 2.f * (x * x + y * y);

    sa = fabsf(sa) + GEPS;
    sb = fabsf(sb) + GEPS;
    sc = fabsf(sc) + GEPS;
    const float a = sa * sa, b = sb * sb, c = sc * sc;

    const float m00 = r00 * r00 * a + r01 * r01 * b + r02 * r02 * c;
    const float m01 = r00 * r10 * a + r01 * r11 * b + r02 * r12 * c;
    const float m02 = r00 * r20 * a + r01 * r21 * b + r02 * r22 * c;
    const float m11 = r10 * r10 * a + r11 * r11 * b + r12 * r12 * c;
    const float m12 = r10 * r20 * a + r11 * r21 * b + r12 * r22 * c;
    const float m22 = r20 * r20 * a + r21 * r21 * b + r22 * r22 * c;

    o[0] = m00; o[1] = m01; o[2] = m02;
    o[3] = m01; o[4] = m11; o[5] = m12;
    o[6] = m02; o[7] = m12; o[8] = m22;
}

__global__ __launch_bounds__(BS) void gaussians_cov_kernel(
    const float4* __restrict__ q,     // [N] float4 (w,x,y,z)
    const float*  __restrict__ s,     // [N*3]
    float*        __restrict__ out,   // [N*9]
    int N)
{
    // warp-private staging: no block-wide barriers anywhere on the hot path
    __shared__ __align__(16) float ssm[WARPS][32 * 3];   // 8 * 384 B  = 3 KB
    __shared__ __align__(16) float osm[WARPS][32 * 9];   // 8 * 1152 B = 9 KB

    const int tid   = threadIdx.x;
    const int wid   = tid >> 5;
    const int lane  = tid & 31;
    const int base  = blockIdx.x * BS + wid * 32;   // this warp's 32 points
    const bool full = (base + 32) <= N;

    if (full) {
        // ---- warp-cooperative loads (all full-width float4, fully sectored) ----
        float4 qv = q[base + lane];                       // coalesced 512B

        // scale slab for this warp: 96 floats = 24 float4 (16B aligned)
        const float4* s4   = reinterpret_cast<const float4*>(s) + (size_t)base * 3 / 4;
        float4* ssm4 = reinterpret_cast<float4*>(ssm[wid]);
        if (lane < 24) ssm4[lane] = s4[lane];
        __syncwarp();

        // ---- compute, stage to warp-private smem (strides 3 & 9: conflict-free) ----
        const float* sp = &ssm[wid][lane * 3];
        cov_from_q(qv, sp[0], sp[1], sp[2], &osm[wid][lane * 9]);
        __syncwarp();

        // ---- warp-cooperative coalesced store: 288 floats = 72 float4 ----
        float4*       out4 = reinterpret_cast<float4*>(out) + (size_t)base * 9 / 4;
        const float4* osm4 = reinterpret_cast<const float4*>(osm[wid]);
        out4[lane]      = osm4[lane];
        out4[32 + lane] = osm4[32 + lane];
        if (lane < 8) out4[64 + lane] = osm4[64 + lane];
    } else {
        const int n = base + lane;
        if (n < N) {
            float4 qv = q[n];
            float obuf[9];
            cov_from_q(qv, s[n * 3 + 0], s[n * 3 + 1], s[n * 3 + 2], obuf);
            float* o = out + (size_t)n * 9;
            #pragma unroll
            for (int j = 0; j < 9; ++j) o[j] = obuf[j];
        }
    }
}

extern "C" void kernel_launch(void* const* d_in, const int* in_sizes, int n_in,
                              void* d_out, int out_size) {
    const float4* q = (const float4*)d_in[0];   // quaternion [N,4]
    const float*  s = (const float*)d_in[1];    // scale [N,3]
    float* out = (float*)d_out;                 // [N,3,3]
    const int N = in_sizes[0] / 4;

    const int grid = (N + BS - 1) / BS;
    gaussians_cov_kernel<<<grid, BS>>>(q, s, out, N);
}